// round 7
// baseline (speedup 1.0000x reference)
#include <cuda_runtime.h>

#define GRID_S 224
#define DIM 512
#define CELLS (GRID_S * GRID_S)
#define TPB 8   // tokens per block

// Scratch (no device allocations allowed).
// g_map is NEVER cleared: lookups are validated against pos, so stale
// contents (zero-init on first call, previous identical scatter after)
// cannot affect the result -> deterministic without an init pass.
__device__ int   g_map[CELLS];
__device__ float g_wt[9 * DIM];

// Fused prep: scatter cell->token map AND transpose w [DIM][3][3] -> g_wt[k][c]
__global__ void prep_kernel(const int* __restrict__ pos,
                            const float* __restrict__ w, int n) {
    int i = blockIdx.x * blockDim.x + threadIdx.x;
    if (i < n) {
        int r = pos[2 * i];
        int c = pos[2 * i + 1];
        g_map[r * GRID_S + c] = i;
    }
    if (i < 9 * DIM) {
        int c = i / 9;
        int k = i % 9;
        g_wt[k * DIM + c] = w[i];
    }
}

// One block per TPB tokens. 128 threads x float4 = 512 channels.
// Phase B runs k-OUTER: one weight float4 per k (amortized over TPB tokens
// in registers), and TPB independent neighbor loads issued back-to-back per
// k-step so L2 latency overlaps across tokens (high MLP).
__global__ __launch_bounds__(128) void sparse_dwconv_kernel(
    const float* __restrict__ x,
    const int*   __restrict__ pos,
    const float* __restrict__ b,
    float*       __restrict__ out,
    int n)
{
    const int tok0 = blockIdx.x * TPB;
    const int tid = threadIdx.x;
    const int lane = tid & 31;
    const int wid  = tid >> 5;

    __shared__ int   s_nbr[TPB][9];   // [t][k]; k=4 -> token itself
    __shared__ float s_wsum[TPB][4];  // per-warp partial channel sums

    // --- Preamble: validated neighbor lookups for all TPB tokens ---
    if (tid < TPB * 9) {
        const int t = tid / 9;
        const int k = tid % 9;
        const int tok = tok0 + t;
        int idx = -1;
        if (tok < n) {
            if (k == 4) {
                idx = tok;   // center tap = the token itself
            } else {
                const int p0 = pos[2 * tok];
                const int p1 = pos[2 * tok + 1];
                const int kh = k / 3;
                const int kw = k % 3;
                const int r = p0 + kw - 1;   // row axis moves with kw
                const int c = p1 + kh - 1;   // col axis moves with kh
                if (r >= 0 && r < GRID_S && c >= 0 && c < GRID_S) {
                    int cand = g_map[r * GRID_S + c];
                    if ((unsigned)cand < (unsigned)n &&
                        pos[2 * cand] == r && pos[2 * cand + 1] == c)
                        idx = cand;
                }
            }
        }
        s_nbr[t][k] = idx;
    }

    const int base = tid * 4;
    const float* xb = x + base;

    // --- Phase A: batched mask reductions (independent chains, ILP) ---
#pragma unroll
    for (int t = 0; t < TPB; ++t) {
        const int tok = tok0 + t;
        float s = 0.0f;
        if (tok < n) {
            const float4 xc = *reinterpret_cast<const float4*>(
                xb + (size_t)tok * DIM);
            s = xc.x + xc.y + xc.z + xc.w;
        }
#pragma unroll
        for (int o = 16; o > 0; o >>= 1)
            s += __shfl_xor_sync(0xffffffffu, s, o);
        if (lane == 0) s_wsum[t][wid] = s;
    }

    const float4 bv = *reinterpret_cast<const float4*>(b + base);

    __syncthreads();   // the ONLY block barrier

    // --- Phase B: k-outer conv. 4 live weight regs, MLP=TPB per k-step ---
    float4 acc[TPB];
#pragma unroll
    for (int t = 0; t < TPB; ++t)
        acc[t] = make_float4(0.f, 0.f, 0.f, 0.f);

#pragma unroll
    for (int k = 0; k < 9; ++k) {
        const float4 wv = *reinterpret_cast<const float4*>(
            g_wt + k * DIM + base);
#pragma unroll
        for (int t = 0; t < TPB; ++t) {
            const int nb = s_nbr[t][k];
            if (nb >= 0) {
                const float4 xv = *reinterpret_cast<const float4*>(
                    xb + (size_t)nb * DIM);
                acc[t].x = fmaf(wv.x, xv.x, acc[t].x);
                acc[t].y = fmaf(wv.y, xv.y, acc[t].y);
                acc[t].z = fmaf(wv.z, xv.z, acc[t].z);
                acc[t].w = fmaf(wv.w, xv.w, acc[t].w);
            }
        }
    }

    // --- Phase C: residual + mask select + store ---
#pragma unroll
    for (int t = 0; t < TPB; ++t) {
        const int tok = tok0 + t;
        if (tok >= n) break;

        const float4 xc = *reinterpret_cast<const float4*>(
            xb + (size_t)tok * DIM);
        const float total = s_wsum[t][0] + s_wsum[t][1]
                          + s_wsum[t][2] + s_wsum[t][3];

        float4 o4;
        if (total != 0.0f) {
            o4.x = xc.x + acc[t].x + bv.x;
            o4.y = xc.y + acc[t].y + bv.y;
            o4.z = xc.z + acc[t].z + bv.z;
            o4.w = xc.w + acc[t].w + bv.w;
        } else {
            o4 = xc;  // masked cell: conv (incl. bias) zeroed, residual only
        }
        *reinterpret_cast<float4*>(out + (size_t)tok * DIM + base) = o4;
    }
}

extern "C" void kernel_launch(void* const* d_in, const int* in_sizes, int n_in,
                              void* d_out, int out_size) {
    const float* x   = (const float*)d_in[0];   // [1, N, 512]
    const int*   pos = (const int*)  d_in[1];   // [N, 2]
    const float* w   = (const float*)d_in[2];   // [512, 1, 3, 3]
    const float* b   = (const float*)d_in[3];   // [512]
    float* out = (float*)d_out;                 // [1, N, 512]

    const int n = in_sizes[1] / 2;

    const int prep_elems = (n > 9 * DIM) ? n : 9 * DIM;
    prep_kernel<<<(prep_elems + 255) / 256, 256>>>(pos, w, n);
    sparse_dwconv_kernel<<<(n + TPB - 1) / TPB, 128>>>(x, pos, b, out, n);
}

// round 8
// speedup vs baseline: 1.1238x; 1.1238x over previous
#include <cuda_runtime.h>

#define GRID_S 224
#define DIM 512
#define CELLS (GRID_S * GRID_S)
#define TPB 4   // tokens per block

// Scratch (no device allocations allowed).
// g_map is NEVER cleared: lookups are validated against pos, so stale
// contents (zero-init on first call, previous identical scatter after)
// cannot affect the result -> deterministic without an init pass.
__device__ int   g_map[CELLS];
__device__ float g_wt[9 * DIM];

// Fused prep: scatter cell->token map AND transpose w [DIM][3][3] -> g_wt[k][c]
__global__ void prep_kernel(const int* __restrict__ pos,
                            const float* __restrict__ w, int n) {
    int i = blockIdx.x * blockDim.x + threadIdx.x;
    if (i < n) {
        int r = pos[2 * i];
        int c = pos[2 * i + 1];
        g_map[r * GRID_S + c] = i;
    }
    if (i < 9 * DIM) {
        int c = i / 9;
        int k = i % 9;
        g_wt[k * DIM + c] = w[i];
    }
}

// One block per TPB tokens. 128 threads x float4 = 512 channels.
// k-outer: one weight float4 per k (amortized over TPB tokens), TPB
// independent neighbor loads per k-step (MLP), registers capped at 64 via
// launch_bounds(128,8) for 50% occupancy. Center row (k==4) is cached so
// phase C does no x reload.
__global__ __launch_bounds__(128, 8) void sparse_dwconv_kernel(
    const float* __restrict__ x,
    const int*   __restrict__ pos,
    const float* __restrict__ b,
    float*       __restrict__ out,
    int n)
{
    const int tok0 = blockIdx.x * TPB;
    const int tid = threadIdx.x;
    const int lane = tid & 31;
    const int wid  = tid >> 5;

    __shared__ int   s_off[TPB][9];   // premultiplied row offsets (nb*DIM), -1 if empty
    __shared__ float s_wsum[TPB][4];  // per-warp partial channel sums

    // --- Preamble: validated neighbor lookups for all TPB tokens ---
    if (tid < TPB * 9) {
        const int t = tid / 9;
        const int k = tid % 9;
        const int tok = tok0 + t;
        int off = -1;
        if (tok < n) {
            if (k == 4) {
                off = tok * DIM;     // center tap = the token itself
            } else {
                const int p0 = pos[2 * tok];
                const int p1 = pos[2 * tok + 1];
                const int kh = k / 3;
                const int kw = k % 3;
                const int r = p0 + kw - 1;   // row axis moves with kw
                const int c = p1 + kh - 1;   // col axis moves with kh
                if (r >= 0 && r < GRID_S && c >= 0 && c < GRID_S) {
                    int cand = g_map[r * GRID_S + c];
                    if ((unsigned)cand < (unsigned)n &&
                        pos[2 * cand] == r && pos[2 * cand + 1] == c)
                        off = cand * DIM;
                }
            }
        }
        s_off[t][k] = off;
    }

    const int base = tid * 4;
    const float* xb = x + base;

    // --- Phase A: batched mask reductions (independent chains, ILP) ---
#pragma unroll
    for (int t = 0; t < TPB; ++t) {
        const int tok = tok0 + t;
        float s = 0.0f;
        if (tok < n) {
            const float4 xc = *reinterpret_cast<const float4*>(
                xb + (size_t)tok * DIM);
            s = xc.x + xc.y + xc.z + xc.w;
        }
#pragma unroll
        for (int o = 16; o > 0; o >>= 1)
            s += __shfl_xor_sync(0xffffffffu, s, o);
        if (lane == 0) s_wsum[t][wid] = s;
    }

    __syncthreads();   // the ONLY block barrier

    // --- Phase B: k-outer conv; cache center row at k==4 ---
    float4 acc[TPB];
    float4 xc[TPB];
#pragma unroll
    for (int t = 0; t < TPB; ++t) {
        acc[t] = make_float4(0.f, 0.f, 0.f, 0.f);
        xc[t]  = make_float4(0.f, 0.f, 0.f, 0.f);
    }

#pragma unroll
    for (int k = 0; k < 9; ++k) {
        const float4 wv = *reinterpret_cast<const float4*>(
            g_wt + k * DIM + base);
#pragma unroll
        for (int t = 0; t < TPB; ++t) {
            const int off = s_off[t][k];
            if (off >= 0) {
                const float4 xv = *reinterpret_cast<const float4*>(xb + off);
                if (k == 4) xc[t] = xv;   // center row doubles as residual
                acc[t].x = fmaf(wv.x, xv.x, acc[t].x);
                acc[t].y = fmaf(wv.y, xv.y, acc[t].y);
                acc[t].z = fmaf(wv.z, xv.z, acc[t].z);
                acc[t].w = fmaf(wv.w, xv.w, acc[t].w);
            }
        }
    }

    const float4 bv = *reinterpret_cast<const float4*>(b + base);

    // --- Phase C: residual + mask select + store (no x reload) ---
#pragma unroll
    for (int t = 0; t < TPB; ++t) {
        const int tok = tok0 + t;
        if (tok >= n) break;

        const float total = s_wsum[t][0] + s_wsum[t][1]
                          + s_wsum[t][2] + s_wsum[t][3];

        float4 o4;
        if (total != 0.0f) {
            o4.x = xc[t].x + acc[t].x + bv.x;
            o4.y = xc[t].y + acc[t].y + bv.y;
            o4.z = xc[t].z + acc[t].z + bv.z;
            o4.w = xc[t].w + acc[t].w + bv.w;
        } else {
            o4 = xc[t];  // masked cell: conv (incl. bias) zeroed, residual only
        }
        *reinterpret_cast<float4*>(out + (size_t)tok * DIM + base) = o4;
    }
}

extern "C" void kernel_launch(void* const* d_in, const int* in_sizes, int n_in,
                              void* d_out, int out_size) {
    const float* x   = (const float*)d_in[0];   // [1, N, 512]
    const int*   pos = (const int*)  d_in[1];   // [N, 2]
    const float* w   = (const float*)d_in[2];   // [512, 1, 3, 3]
    const float* b   = (const float*)d_in[3];   // [512]
    float* out = (float*)d_out;                 // [1, N, 512]

    const int n = in_sizes[1] / 2;

    const int prep_elems = (n > 9 * DIM) ? n : 9 * DIM;
    prep_kernel<<<(prep_elems + 255) / 256, 256>>>(pos, w, n);
    sparse_dwconv_kernel<<<(n + TPB - 1) / TPB, 128>>>(x, pos, b, out, n);
}